// round 1
// baseline (speedup 1.0000x reference)
#include <cuda_runtime.h>
#include <math.h>

#define B_SZ 4
#define T_SZ 2048
#define D_MODEL 1024
#define HEADS 16
#define DH 64
#define HALF 32
#define M_ROWS (B_SZ * T_SZ)          // 8192
#define N_QKV (3 * D_MODEL)           // 3072

// ---------------- scratch (device globals; no allocation allowed) ----------
__device__ float g_qkv[M_ROWS * N_QKV];                 // [8192, 3072]
__device__ float g_q[B_SZ * HEADS * T_SZ * DH];         // [b,h,t,d]
__device__ float g_k[B_SZ * HEADS * T_SZ * DH];
__device__ float g_v[B_SZ * HEADS * T_SZ * DH];
__device__ float g_attn[M_ROWS * D_MODEL];              // [b,t,h*dh]
__device__ float g_sin[T_SZ * HALF];
__device__ float g_cos[T_SZ * HALF];

// ---------------- generic SGEMM + bias: C = A@B + bias --------------------
// BM=BN=128, BK=16, 256 threads, 8x8 microtile per thread.
__global__ void __launch_bounds__(256) sgemm_bias_kernel(
    const float* __restrict__ A, const float* __restrict__ Bm,
    const float* __restrict__ bias, float* __restrict__ C,
    int M, int N, int K)
{
    const int BM = 128, BN = 128, BK = 16;
    __shared__ float As[BK][BM];   // transposed A tile
    __shared__ float Bs[BK][BN];

    int tid = threadIdx.x;
    int tx = tid & 15;
    int ty = tid >> 4;
    int rowBlk = blockIdx.y * BM;
    int colBlk = blockIdx.x * BN;

    float acc[8][8];
#pragma unroll
    for (int i = 0; i < 8; ++i)
#pragma unroll
        for (int j = 0; j < 8; ++j) acc[i][j] = 0.0f;

    for (int k0 = 0; k0 < K; k0 += BK) {
        // load A tile (BM x BK) transposed into As
#pragma unroll
        for (int it = 0; it < 2; ++it) {
            int idx = tid + it * 256;             // 0..511 float4s
            int r = idx >> 2;                     // 0..127
            int c4 = (idx & 3) * 4;               // 0,4,8,12
            float4 v = *(const float4*)&A[(size_t)(rowBlk + r) * K + k0 + c4];
            As[c4 + 0][r] = v.x;
            As[c4 + 1][r] = v.y;
            As[c4 + 2][r] = v.z;
            As[c4 + 3][r] = v.w;
        }
        // load B tile (BK x BN)
#pragma unroll
        for (int it = 0; it < 2; ++it) {
            int idx = tid + it * 256;             // 0..511 float4s
            int r = idx >> 5;                     // 0..15
            int c4 = (idx & 31) * 4;              // 0..124
            *(float4*)&Bs[r][c4] = *(const float4*)&Bm[(size_t)(k0 + r) * N + colBlk + c4];
        }
        __syncthreads();

#pragma unroll
        for (int kk = 0; kk < BK; ++kk) {
            float a[8], b[8];
            *(float4*)&a[0] = *(const float4*)&As[kk][ty * 8];
            *(float4*)&a[4] = *(const float4*)&As[kk][ty * 8 + 4];
            *(float4*)&b[0] = *(const float4*)&Bs[kk][tx * 8];
            *(float4*)&b[4] = *(const float4*)&Bs[kk][tx * 8 + 4];
#pragma unroll
            for (int i = 0; i < 8; ++i)
#pragma unroll
                for (int j = 0; j < 8; ++j)
                    acc[i][j] += a[i] * b[j];
        }
        __syncthreads();
    }

    float bj[8];
#pragma unroll
    for (int j = 0; j < 8; ++j) bj[j] = bias[colBlk + tx * 8 + j];

#pragma unroll
    for (int i = 0; i < 8; ++i) {
        int r = rowBlk + ty * 8 + i;
        float4 v0 = make_float4(acc[i][0] + bj[0], acc[i][1] + bj[1],
                                acc[i][2] + bj[2], acc[i][3] + bj[3]);
        float4 v1 = make_float4(acc[i][4] + bj[4], acc[i][5] + bj[5],
                                acc[i][6] + bj[6], acc[i][7] + bj[7]);
        *(float4*)&C[(size_t)r * N + colBlk + tx * 8]     = v0;
        *(float4*)&C[(size_t)r * N + colBlk + tx * 8 + 4] = v1;
    }
}

// ---------------- RoPE sin/cos table ---------------------------------------
__global__ void rope_table_kernel()
{
    int i = blockIdx.x * blockDim.x + threadIdx.x;
    if (i >= T_SZ * HALF) return;
    int t = i / HALF;
    int d = i % HALF;
    double invf = pow(10000.0, -(double)d / (double)HALF);
    float fr = (float)t * (float)invf;
    g_sin[i] = sinf(fr);
    g_cos[i] = cosf(fr);
}

// ---------------- RoPE apply + head relayout -------------------------------
// qkv[b,t, {q|k|v} h dh] -> q/k/v [b,h,t,dh], with RoPE on q,k.
__global__ void rope_split_kernel()
{
    int idx = blockIdx.x * blockDim.x + threadIdx.x;
    const int TOTAL = B_SZ * T_SZ * HEADS * HALF;
    if (idx >= TOTAL) return;
    int d = idx & (HALF - 1);
    int h = (idx >> 5) & (HEADS - 1);
    int t = (idx >> 9) & (T_SZ - 1);
    int b = idx >> 20;

    float s = g_sin[t * HALF + d];
    float c = g_cos[t * HALF + d];

    size_t row = (size_t)(b * T_SZ + t) * N_QKV;
    size_t orow = (size_t)((b * HEADS + h) * T_SZ + t) * DH;

    const float* qp = g_qkv + row + h * DH;
    float x1 = qp[d], x2 = qp[d + HALF];
    g_q[orow + d]        = x1 * c - x2 * s;
    g_q[orow + d + HALF] = x1 * s + x2 * c;

    const float* kp = g_qkv + row + D_MODEL + h * DH;
    x1 = kp[d]; x2 = kp[d + HALF];
    g_k[orow + d]        = x1 * c - x2 * s;
    g_k[orow + d + HALF] = x1 * s + x2 * c;

    const float* vp = g_qkv + row + 2 * D_MODEL + h * DH;
    g_v[orow + d]        = vp[d];
    g_v[orow + d + HALF] = vp[d + HALF];
}

// ---------------- Flash attention (fp32) -----------------------------------
// BM=128 queries per block, BN=64 keys per tile, 128 threads, 8x8 microtiles.
#define BMA 128
#define BNA 64
#define ATTN_SMEM ((DH * BMA + DH * BNA + BNA * DH + BNA * BMA) * 4)  // 96KB

__global__ void __launch_bounds__(128, 1) attn_fwd_kernel()
{
    extern __shared__ float sm[];
    float* Qt = sm;                         // [DH][BMA]
    float* Kt = Qt + DH * BMA;              // [DH][BNA]
    float* Vs = Kt + DH * BNA;              // [BNA][DH]
    float* Pt = Vs + BNA * DH;              // [BNA][BMA]

    int tid = threadIdx.x;
    int tr = tid >> 3;          // 0..15 -> query rows tr*8..
    int tc = tid & 7;           // 0..7  -> key cols / out dims tc*8..
    int bh = blockIdx.y;
    int q0 = blockIdx.x * BMA;

    const float* Qb = g_q + ((size_t)bh * T_SZ + q0) * DH;
    const float* Kb = g_k + (size_t)bh * T_SZ * DH;
    const float* Vb = g_v + (size_t)bh * T_SZ * DH;

    // load Q tile transposed
#pragma unroll
    for (int it = 0; it < 16; ++it) {
        int f = tid + it * 128;             // 0..2047 float4s: [128 rows][16 f4]
        int r = f >> 4;
        int c4 = (f & 15) * 4;
        float4 v = *(const float4*)&Qb[r * DH + c4];
        Qt[(c4 + 0) * BMA + r] = v.x;
        Qt[(c4 + 1) * BMA + r] = v.y;
        Qt[(c4 + 2) * BMA + r] = v.z;
        Qt[(c4 + 3) * BMA + r] = v.w;
    }

    float o[8][8];
    float mi[8], li[8];
#pragma unroll
    for (int i = 0; i < 8; ++i) {
        mi[i] = -INFINITY;
        li[i] = 0.0f;
#pragma unroll
        for (int j = 0; j < 8; ++j) o[i][j] = 0.0f;
    }

    const float scale = 0.125f;  // 1/sqrt(64)

    for (int kt = 0; kt < T_SZ / BNA; ++kt) {
        __syncthreads();   // previous PV done before overwriting K/V/P
        const float* Kp = Kb + (size_t)kt * BNA * DH;
        const float* Vp = Vb + (size_t)kt * BNA * DH;
#pragma unroll
        for (int it = 0; it < 8; ++it) {
            int f = tid + it * 128;         // 0..1023 float4s: [64 rows][16 f4]
            int r = f >> 4;
            int c4 = (f & 15) * 4;
            float4 v = *(const float4*)&Kp[r * DH + c4];
            Kt[(c4 + 0) * BNA + r] = v.x;
            Kt[(c4 + 1) * BNA + r] = v.y;
            Kt[(c4 + 2) * BNA + r] = v.z;
            Kt[(c4 + 3) * BNA + r] = v.w;
            *(float4*)&Vs[r * DH + c4] = *(const float4*)&Vp[r * DH + c4];
        }
        __syncthreads();

        // S = Q K^T  (8x8 microtile)
        float s[8][8];
#pragma unroll
        for (int i = 0; i < 8; ++i)
#pragma unroll
            for (int j = 0; j < 8; ++j) s[i][j] = 0.0f;

#pragma unroll 8
        for (int d = 0; d < DH; ++d) {
            float a[8], b[8];
            *(float4*)&a[0] = *(const float4*)&Qt[d * BMA + tr * 8];
            *(float4*)&a[4] = *(const float4*)&Qt[d * BMA + tr * 8 + 4];
            *(float4*)&b[0] = *(const float4*)&Kt[d * BNA + tc * 8];
            *(float4*)&b[4] = *(const float4*)&Kt[d * BNA + tc * 8 + 4];
#pragma unroll
            for (int i = 0; i < 8; ++i)
#pragma unroll
                for (int j = 0; j < 8; ++j)
                    s[i][j] += a[i] * b[j];
        }

        // online softmax per query row (8 threads per row, shfl width 8)
#pragma unroll
        for (int i = 0; i < 8; ++i) {
            float mx = -INFINITY;
#pragma unroll
            for (int j = 0; j < 8; ++j) {
                s[i][j] *= scale;
                mx = fmaxf(mx, s[i][j]);
            }
            mx = fmaxf(mx, __shfl_xor_sync(0xffffffffu, mx, 4, 8));
            mx = fmaxf(mx, __shfl_xor_sync(0xffffffffu, mx, 2, 8));
            mx = fmaxf(mx, __shfl_xor_sync(0xffffffffu, mx, 1, 8));
            float mnew = fmaxf(mi[i], mx);
            float corr = __expf(mi[i] - mnew);
            mi[i] = mnew;
            float rs = 0.0f;
#pragma unroll
            for (int j = 0; j < 8; ++j) {
                float p = __expf(s[i][j] - mnew);
                s[i][j] = p;
                rs += p;
            }
            rs += __shfl_xor_sync(0xffffffffu, rs, 4, 8);
            rs += __shfl_xor_sync(0xffffffffu, rs, 2, 8);
            rs += __shfl_xor_sync(0xffffffffu, rs, 1, 8);
            li[i] = li[i] * corr + rs;
#pragma unroll
            for (int j = 0; j < 8; ++j) o[i][j] *= corr;
        }

        // store P transposed: Pt[k][r]
#pragma unroll
        for (int j = 0; j < 8; ++j) {
            *(float4*)&Pt[(tc * 8 + j) * BMA + tr * 8] =
                make_float4(s[0][j], s[1][j], s[2][j], s[3][j]);
            *(float4*)&Pt[(tc * 8 + j) * BMA + tr * 8 + 4] =
                make_float4(s[4][j], s[5][j], s[6][j], s[7][j]);
        }
        __syncthreads();

        // O += P @ V
#pragma unroll 8
        for (int k = 0; k < BNA; ++k) {
            float a[8], b[8];
            *(float4*)&a[0] = *(const float4*)&Pt[k * BMA + tr * 8];
            *(float4*)&a[4] = *(const float4*)&Pt[k * BMA + tr * 8 + 4];
            *(float4*)&b[0] = *(const float4*)&Vs[k * DH + tc * 8];
            *(float4*)&b[4] = *(const float4*)&Vs[k * DH + tc * 8 + 4];
#pragma unroll
            for (int i = 0; i < 8; ++i)
#pragma unroll
                for (int j = 0; j < 8; ++j)
                    o[i][j] += a[i] * b[j];
        }
    }

    // epilogue: normalize, write [b,t,h*dh]
    int b_ = bh / HEADS;
    int h_ = bh % HEADS;
#pragma unroll
    for (int i = 0; i < 8; ++i) {
        float invl = 1.0f / li[i];
        int t = q0 + tr * 8 + i;
        float* op = g_attn + (size_t)(b_ * T_SZ + t) * D_MODEL + h_ * DH + tc * 8;
        *(float4*)op = make_float4(o[i][0] * invl, o[i][1] * invl,
                                   o[i][2] * invl, o[i][3] * invl);
        *(float4*)(op + 4) = make_float4(o[i][4] * invl, o[i][5] * invl,
                                         o[i][6] * invl, o[i][7] * invl);
    }
}

// ---------------- launcher --------------------------------------------------
extern "C" void kernel_launch(void* const* d_in, const int* in_sizes, int n_in,
                              void* d_out, int out_size)
{
    const float* x     = (const float*)d_in[0];   // [4,2048,1024]
    const float* Wqkv  = (const float*)d_in[1];   // [1024,3072]
    const float* bqkv  = (const float*)d_in[2];   // [3072]
    const float* Wproj = (const float*)d_in[3];   // [1024,1024]
    const float* bproj = (const float*)d_in[4];   // [1024]
    float* out = (float*)d_out;

    float* qkv_ptr = nullptr;
    float* attn_ptr = nullptr;
    cudaGetSymbolAddress((void**)&qkv_ptr, g_qkv);
    cudaGetSymbolAddress((void**)&attn_ptr, g_attn);

    cudaFuncSetAttribute(attn_fwd_kernel,
                         cudaFuncAttributeMaxDynamicSharedMemorySize, ATTN_SMEM);

    // 1) QKV GEMM
    {
        dim3 grid(N_QKV / 128, M_ROWS / 128);
        sgemm_bias_kernel<<<grid, 256>>>(x, Wqkv, bqkv, qkv_ptr,
                                         M_ROWS, N_QKV, D_MODEL);
    }
    // 2) RoPE table + apply/relayout
    {
        int n = T_SZ * HALF;
        rope_table_kernel<<<(n + 255) / 256, 256>>>();
        int total = B_SZ * T_SZ * HEADS * HALF;
        rope_split_kernel<<<(total + 255) / 256, 256>>>();
    }
    // 3) flash attention
    {
        dim3 grid(T_SZ / BMA, B_SZ * HEADS);
        attn_fwd_kernel<<<grid, 128, ATTN_SMEM>>>();
    }
    // 4) output projection
    {
        dim3 grid(D_MODEL / 128, M_ROWS / 128);
        sgemm_bias_kernel<<<grid, 256>>>(attn_ptr, Wproj, bproj, out,
                                         M_ROWS, D_MODEL, D_MODEL);
    }
}

// round 2
// speedup vs baseline: 2.9035x; 2.9035x over previous
#include <cuda_runtime.h>
#include <math.h>
#include <stdint.h>

#define B_SZ 4
#define T_SZ 2048
#define D_MODEL 1024
#define HEADS 16
#define DH 64
#define HALF 32
#define M_ROWS (B_SZ * T_SZ)          // 8192
#define N_QKV (3 * D_MODEL)           // 3072

// ---------------- scratch ---------------------------------------------------
__device__ float g_qkv[M_ROWS * N_QKV];
__device__ float g_q[B_SZ * HEADS * T_SZ * DH];
__device__ float g_k[B_SZ * HEADS * T_SZ * DH];
__device__ float g_v[B_SZ * HEADS * T_SZ * DH];
__device__ float g_attn[M_ROWS * D_MODEL];
__device__ float g_sin[T_SZ * HALF];
__device__ float g_cos[T_SZ * HALF];

// ---------------- tf32 helpers ---------------------------------------------
__device__ __forceinline__ uint32_t f2tf(float x) {
    uint32_t r;
    asm("cvt.rna.tf32.f32 %0, %1;" : "=r"(r) : "f"(x));
    return r;
}
// D += A(16x8) * B(8x8), tf32 in, fp32 accum
__device__ __forceinline__ void mma8(float* d, const uint32_t* a, const uint32_t* b) {
    asm volatile(
        "mma.sync.aligned.m16n8k8.row.col.f32.tf32.tf32.f32 "
        "{%0,%1,%2,%3}, {%4,%5,%6,%7}, {%8,%9}, {%0,%1,%2,%3};\n"
        : "+f"(d[0]), "+f"(d[1]), "+f"(d[2]), "+f"(d[3])
        : "r"(a[0]), "r"(a[1]), "r"(a[2]), "r"(a[3]), "r"(b[0]), "r"(b[1]));
}

// ---------------- TF32 GEMM + bias: C = A@B + bias --------------------------
// BM=128, BN=128, BK=32, 256 threads = 8 warps (2m x 4n), warp tile 64x32.
#define GSA 36     // As row stride (floats): (36*p+q)%32 = 4p+q -> conflict-free
#define GSB 136    // Bs row stride: (136*q+p)%32 = 8q+p -> conflict-free
__global__ void __launch_bounds__(256) gemm_tf32_kernel(
    const float* __restrict__ A, const float* __restrict__ Bm,
    const float* __restrict__ bias, float* __restrict__ C,
    int M, int N, int K)
{
    __shared__ float As[128 * GSA];  // 18432 B
    __shared__ float Bs[32 * GSB];   // 17408 B

    int tid = threadIdx.x;
    int warp = tid >> 5, lane = tid & 31;
    int wm = warp >> 2;          // 0..1
    int wn = warp & 3;           // 0..3
    int p = lane >> 2, q = lane & 3;
    int rowBlk = blockIdx.y * 128, colBlk = blockIdx.x * 128;

    float acc[4][4][4];
#pragma unroll
    for (int mt = 0; mt < 4; ++mt)
#pragma unroll
        for (int nt = 0; nt < 4; ++nt)
#pragma unroll
            for (int c = 0; c < 4; ++c) acc[mt][nt][c] = 0.0f;

    for (int k0 = 0; k0 < K; k0 += 32) {
#pragma unroll
        for (int i = 0; i < 4; ++i) {
            int f = tid + i * 256;               // 1024 float4s of A (128x32)
            int r = f >> 3, c4 = (f & 7) * 4;
            *(float4*)&As[r * GSA + c4] =
                *(const float4*)&A[(size_t)(rowBlk + r) * K + k0 + c4];
        }
#pragma unroll
        for (int i = 0; i < 4; ++i) {
            int f = tid + i * 256;               // 1024 float4s of B (32x128)
            int r = f >> 5, c4 = (f & 31) * 4;
            *(float4*)&Bs[r * GSB + c4] =
                *(const float4*)&Bm[(size_t)(k0 + r) * N + colBlk + c4];
        }
        __syncthreads();

#pragma unroll
        for (int ks = 0; ks < 4; ++ks) {
            int kk = ks * 8;
            uint32_t af[4][4], bf[4][2];
#pragma unroll
            for (int mt = 0; mt < 4; ++mt) {
                const float* b = &As[(wm * 64 + mt * 16 + p) * GSA + kk + q];
                af[mt][0] = f2tf(b[0]);
                af[mt][1] = f2tf(b[8 * GSA]);
                af[mt][2] = f2tf(b[4]);
                af[mt][3] = f2tf(b[8 * GSA + 4]);
            }
#pragma unroll
            for (int nt = 0; nt < 4; ++nt) {
                const float* b = &Bs[(kk + q) * GSB + wn * 32 + nt * 8 + p];
                bf[nt][0] = f2tf(b[0]);
                bf[nt][1] = f2tf(b[4 * GSB]);
            }
#pragma unroll
            for (int mt = 0; mt < 4; ++mt)
#pragma unroll
                for (int nt = 0; nt < 4; ++nt)
                    mma8(acc[mt][nt], af[mt], bf[nt]);
        }
        __syncthreads();
    }

#pragma unroll
    for (int mt = 0; mt < 4; ++mt) {
#pragma unroll
        for (int nt = 0; nt < 4; ++nt) {
            int r0 = rowBlk + wm * 64 + mt * 16 + p;
            int c0 = colBlk + wn * 32 + nt * 8 + 2 * q;
            float b0 = bias[c0], b1 = bias[c0 + 1];
            *(float2*)&C[(size_t)r0 * N + c0] =
                make_float2(acc[mt][nt][0] + b0, acc[mt][nt][1] + b1);
            *(float2*)&C[(size_t)(r0 + 8) * N + c0] =
                make_float2(acc[mt][nt][2] + b0, acc[mt][nt][3] + b1);
        }
    }
}

// ---------------- RoPE table ------------------------------------------------
__global__ void rope_table_kernel()
{
    int i = blockIdx.x * blockDim.x + threadIdx.x;
    if (i >= T_SZ * HALF) return;
    int t = i / HALF;
    int d = i % HALF;
    double invf = pow(10000.0, -(double)d / (double)HALF);
    float fr = (float)t * (float)invf;
    g_sin[i] = sinf(fr);
    g_cos[i] = cosf(fr);
}

// ---------------- RoPE apply + relayout -------------------------------------
__global__ void rope_split_kernel()
{
    int idx = blockIdx.x * blockDim.x + threadIdx.x;
    const int TOTAL = B_SZ * T_SZ * HEADS * HALF;
    if (idx >= TOTAL) return;
    int d = idx & (HALF - 1);
    int h = (idx >> 5) & (HEADS - 1);
    int t = (idx >> 9) & (T_SZ - 1);
    int b = idx >> 20;

    float s = g_sin[t * HALF + d];
    float c = g_cos[t * HALF + d];

    size_t row = (size_t)(b * T_SZ + t) * N_QKV;
    size_t orow = (size_t)((b * HEADS + h) * T_SZ + t) * DH;

    const float* qp = g_qkv + row + h * DH;
    float x1 = qp[d], x2 = qp[d + HALF];
    g_q[orow + d]        = x1 * c - x2 * s;
    g_q[orow + d + HALF] = x1 * s + x2 * c;

    const float* kp = g_qkv + row + D_MODEL + h * DH;
    x1 = kp[d]; x2 = kp[d + HALF];
    g_k[orow + d]        = x1 * c - x2 * s;
    g_k[orow + d + HALF] = x1 * s + x2 * c;

    const float* vp = g_qkv + row + 2 * D_MODEL + h * DH;
    g_v[orow + d]        = vp[d];
    g_v[orow + d + HALF] = vp[d + HALF];
}

// ---------------- Flash attention, TF32 MMA ---------------------------------
// 128 queries/block, 64 keys/iter, 256 threads = 8 warps; warp owns 16 q-rows.
// smem strides chosen so all fragment LDS are bank-conflict-free.
#define SQ 68   // (68*p+q)%32 = 4p+q distinct
#define SK 68
#define SV 72   // (72*q+p)%32 = 8q+p distinct
#define SP 68
#define OFF_Q 0
#define OFF_K (128 * SQ)                 // 8704
#define OFF_V (OFF_K + 64 * SK)          // 13056
#define OFF_P (OFF_V + 64 * SV)          // 17664
#define ATTN_SMEM ((OFF_P + 128 * SP) * 4)   // 105472 B

__global__ void __launch_bounds__(256, 1) attn_tf32_kernel()
{
    extern __shared__ float sm[];
    float* Qs = sm + OFF_Q;
    float* Ks = sm + OFF_K;
    float* Vs = sm + OFF_V;
    float* Ps = sm + OFF_P;

    int tid = threadIdx.x;
    int warp = tid >> 5, lane = tid & 31;
    int p = lane >> 2, q = lane & 3;
    int m0 = warp * 16;
    int bh = blockIdx.y;
    int q0 = blockIdx.x * 128;

    const float* Qb = g_q + ((size_t)bh * T_SZ + q0) * DH;
    const float* Kb = g_k + (size_t)bh * T_SZ * DH;
    const float* Vb = g_v + (size_t)bh * T_SZ * DH;

#pragma unroll
    for (int i = 0; i < 8; ++i) {
        int f = tid + i * 256;               // 2048 float4s: Q 128x64
        int r = f >> 4, c4 = (f & 15) * 4;
        *(float4*)&Qs[r * SQ + c4] = *(const float4*)&Qb[r * DH + c4];
    }

    float o[8][4];
    float mA = -INFINITY, mB = -INFINITY, lA = 0.0f, lB = 0.0f;
#pragma unroll
    for (int nt = 0; nt < 8; ++nt)
#pragma unroll
        for (int c = 0; c < 4; ++c) o[nt][c] = 0.0f;

    const float scale = 0.125f;

    for (int kt = 0; kt < T_SZ / 64; ++kt) {
        __syncthreads();
        const float* Kp = Kb + (size_t)kt * 64 * DH;
        const float* Vp = Vb + (size_t)kt * 64 * DH;
#pragma unroll
        for (int i = 0; i < 4; ++i) {
            int f = tid + i * 256;           // 1024 float4s: 64x64
            int r = f >> 4, c4 = (f & 15) * 4;
            *(float4*)&Ks[r * SK + c4] = *(const float4*)&Kp[r * DH + c4];
            *(float4*)&Vs[r * SV + c4] = *(const float4*)&Vp[r * DH + c4];
        }
        __syncthreads();

        // ---- S = Q K^T : warp computes 16 x 64 ----
        float s[8][4];
#pragma unroll
        for (int nt = 0; nt < 8; ++nt)
#pragma unroll
            for (int c = 0; c < 4; ++c) s[nt][c] = 0.0f;

#pragma unroll
        for (int ks = 0; ks < 8; ++ks) {
            int kk = ks * 8;
            uint32_t a[4];
            const float* ab = &Qs[(m0 + p) * SQ + kk + q];
            a[0] = f2tf(ab[0]);
            a[1] = f2tf(ab[8 * SQ]);
            a[2] = f2tf(ab[4]);
            a[3] = f2tf(ab[8 * SQ + 4]);
#pragma unroll
            for (int nt = 0; nt < 8; ++nt) {
                uint32_t b[2];
                const float* bb = &Ks[(nt * 8 + p) * SK + kk + q];
                b[0] = f2tf(bb[0]);
                b[1] = f2tf(bb[4]);
                mma8(s[nt], a, b);
            }
        }

        // ---- online softmax (rows p and p+8; 4 lanes per row, width-4) ----
        float mxA = -INFINITY, mxB = -INFINITY;
#pragma unroll
        for (int nt = 0; nt < 8; ++nt) {
            s[nt][0] *= scale; s[nt][1] *= scale;
            s[nt][2] *= scale; s[nt][3] *= scale;
            mxA = fmaxf(mxA, fmaxf(s[nt][0], s[nt][1]));
            mxB = fmaxf(mxB, fmaxf(s[nt][2], s[nt][3]));
        }
        mxA = fmaxf(mxA, __shfl_xor_sync(0xffffffffu, mxA, 1));
        mxA = fmaxf(mxA, __shfl_xor_sync(0xffffffffu, mxA, 2));
        mxB = fmaxf(mxB, __shfl_xor_sync(0xffffffffu, mxB, 1));
        mxB = fmaxf(mxB, __shfl_xor_sync(0xffffffffu, mxB, 2));
        float mnA = fmaxf(mA, mxA), mnB = fmaxf(mB, mxB);
        float cA = __expf(mA - mnA), cB = __expf(mB - mnB);
        mA = mnA; mB = mnB;
        float rsA = 0.0f, rsB = 0.0f;
#pragma unroll
        for (int nt = 0; nt < 8; ++nt) {
            s[nt][0] = __expf(s[nt][0] - mnA); rsA += s[nt][0];
            s[nt][1] = __expf(s[nt][1] - mnA); rsA += s[nt][1];
            s[nt][2] = __expf(s[nt][2] - mnB); rsB += s[nt][2];
            s[nt][3] = __expf(s[nt][3] - mnB); rsB += s[nt][3];
        }
        rsA += __shfl_xor_sync(0xffffffffu, rsA, 1);
        rsA += __shfl_xor_sync(0xffffffffu, rsA, 2);
        rsB += __shfl_xor_sync(0xffffffffu, rsB, 1);
        rsB += __shfl_xor_sync(0xffffffffu, rsB, 2);
        lA = lA * cA + rsA;
        lB = lB * cB + rsB;
#pragma unroll
        for (int nt = 0; nt < 8; ++nt) {
            o[nt][0] *= cA; o[nt][1] *= cA;
            o[nt][2] *= cB; o[nt][3] *= cB;
        }

        // ---- P -> warp-private smem strip (C-frag layout -> A-frag layout)
#pragma unroll
        for (int nt = 0; nt < 8; ++nt) {
            *(float2*)&Ps[(m0 + p) * SP + nt * 8 + 2 * q] =
                make_float2(s[nt][0], s[nt][1]);
            *(float2*)&Ps[(m0 + p + 8) * SP + nt * 8 + 2 * q] =
                make_float2(s[nt][2], s[nt][3]);
        }
        __syncwarp();

        // ---- O += P @ V ----
#pragma unroll
        for (int ks = 0; ks < 8; ++ks) {
            int kk = ks * 8;
            uint32_t a[4];
            const float* ab = &Ps[(m0 + p) * SP + kk + q];
            a[0] = f2tf(ab[0]);
            a[1] = f2tf(ab[8 * SP]);
            a[2] = f2tf(ab[4]);
            a[3] = f2tf(ab[8 * SP + 4]);
#pragma unroll
            for (int nt = 0; nt < 8; ++nt) {
                uint32_t b[2];
                const float* bb = &Vs[(kk + q) * SV + nt * 8 + p];
                b[0] = f2tf(bb[0]);
                b[1] = f2tf(bb[4 * SV]);
                mma8(o[nt], a, b);
            }
        }
    }

    // ---- epilogue: normalize, write [b,t,h*dh] ----
    int b_ = bh / HEADS;
    int h_ = bh % HEADS;
    float ivA = 1.0f / lA, ivB = 1.0f / lB;
    int t = q0 + m0 + p;
#pragma unroll
    for (int nt = 0; nt < 8; ++nt) {
        float* op = g_attn + (size_t)(b_ * T_SZ + t) * D_MODEL + h_ * DH + nt * 8 + 2 * q;
        *(float2*)op = make_float2(o[nt][0] * ivA, o[nt][1] * ivA);
        *(float2*)(op + 8 * D_MODEL) = make_float2(o[nt][2] * ivB, o[nt][3] * ivB);
    }
}

// ---------------- launcher --------------------------------------------------
extern "C" void kernel_launch(void* const* d_in, const int* in_sizes, int n_in,
                              void* d_out, int out_size)
{
    const float* x     = (const float*)d_in[0];
    const float* Wqkv  = (const float*)d_in[1];
    const float* bqkv  = (const float*)d_in[2];
    const float* Wproj = (const float*)d_in[3];
    const float* bproj = (const float*)d_in[4];
    float* out = (float*)d_out;

    float* qkv_ptr = nullptr;
    float* attn_ptr = nullptr;
    cudaGetSymbolAddress((void**)&qkv_ptr, g_qkv);
    cudaGetSymbolAddress((void**)&attn_ptr, g_attn);

    cudaFuncSetAttribute(attn_tf32_kernel,
                         cudaFuncAttributeMaxDynamicSharedMemorySize, ATTN_SMEM);

    // 1) QKV GEMM
    {
        dim3 grid(N_QKV / 128, M_ROWS / 128);
        gemm_tf32_kernel<<<grid, 256>>>(x, Wqkv, bqkv, qkv_ptr,
                                        M_ROWS, N_QKV, D_MODEL);
    }
    // 2) RoPE
    {
        int n = T_SZ * HALF;
        rope_table_kernel<<<(n + 255) / 256, 256>>>();
        int total = B_SZ * T_SZ * HEADS * HALF;
        rope_split_kernel<<<(total + 255) / 256, 256>>>();
    }
    // 3) flash attention
    {
        dim3 grid(T_SZ / 128, B_SZ * HEADS);
        attn_tf32_kernel<<<grid, 256, ATTN_SMEM>>>();
    }
    // 4) output projection
    {
        dim3 grid(D_MODEL / 128, M_ROWS / 128);
        gemm_tf32_kernel<<<grid, 256>>>(attn_ptr, Wproj, bproj, out,
                                        M_ROWS, D_MODEL, D_MODEL);
    }
}

// round 5
// speedup vs baseline: 3.3444x; 1.1518x over previous
#include <cuda_runtime.h>
#include <math.h>
#include <stdint.h>

#define B_SZ 4
#define T_SZ 2048
#define D_MODEL 1024
#define HEADS 16
#define DH 64
#define HALF 32
#define M_ROWS (B_SZ * T_SZ)          // 8192
#define N_QKV (3 * D_MODEL)           // 3072

// ---------------- scratch ---------------------------------------------------
__device__ float g_qkv[M_ROWS * N_QKV];
__device__ float g_q[B_SZ * HEADS * T_SZ * DH];
__device__ float g_k[B_SZ * HEADS * T_SZ * DH];
__device__ float g_v[B_SZ * HEADS * T_SZ * DH];
__device__ float g_attn[M_ROWS * D_MODEL];
__device__ float g_sin[T_SZ * HALF];
__device__ float g_cos[T_SZ * HALF];

// ---------------- helpers ---------------------------------------------------
__device__ __forceinline__ uint32_t f2tf(float x) {
    uint32_t r;
    asm("cvt.rna.tf32.f32 %0, %1;" : "=r"(r) : "f"(x));
    return r;
}
__device__ __forceinline__ uint32_t sptr(const void* p) {
    return (uint32_t)__cvta_generic_to_shared(p);
}
__device__ __forceinline__ void ldm4(uint32_t* r, uint32_t a) {
    asm volatile("ldmatrix.sync.aligned.m8n8.x4.shared.b16 {%0,%1,%2,%3}, [%4];"
                 : "=r"(r[0]), "=r"(r[1]), "=r"(r[2]), "=r"(r[3]) : "r"(a));
}
// D += A(16x8) * B(8x8), tf32 bits in, fp32 accum
__device__ __forceinline__ void mma8(float* d, const uint32_t* a,
                                     uint32_t b0, uint32_t b1) {
    asm volatile(
        "mma.sync.aligned.m16n8k8.row.col.f32.tf32.tf32.f32 "
        "{%0,%1,%2,%3}, {%4,%5,%6,%7}, {%8,%9}, {%0,%1,%2,%3};\n"
        : "+f"(d[0]), "+f"(d[1]), "+f"(d[2]), "+f"(d[3])
        : "r"(a[0]), "r"(a[1]), "r"(a[2]), "r"(a[3]), "r"(b0), "r"(b1));
}

// ---------------- TF32 GEMM + bias ------------------------------------------
// BM=128, BN=128, BK=32, 256 threads = 8 warps (2m x 4n), warp tile 64x32.
// As: [m][k] u32(tf32) stride 36; Bs: [k][n] u32(tf32) stride 136.
#define GSA 36
#define GSB 136
__global__ void __launch_bounds__(256, 2) gemm_tf32_kernel(
    const float* __restrict__ A, const float* __restrict__ Bm,
    const float* __restrict__ bias, float* __restrict__ C,
    int M, int N, int K)
{
    __shared__ uint32_t As[128 * GSA];
    __shared__ uint32_t Bs[32 * GSB];

    int tid = threadIdx.x;
    int warp = tid >> 5, lane = tid & 31;
    int wm = warp >> 2, wn = warp & 3;
    int p = lane >> 2, q = lane & 3;
    int rowBlk = blockIdx.y * 128, colBlk = blockIdx.x * 128;

    uint32_t abase[4];
#pragma unroll
    for (int mt = 0; mt < 4; ++mt)
        abase[mt] = sptr(As) +
            4 * ((wm * 64 + mt * 16 + (lane & 15)) * GSA + ((lane >> 4) << 2));
    int bb0 = q * GSB + wn * 32 + p;

    float acc[4][4][4];
#pragma unroll
    for (int mt = 0; mt < 4; ++mt)
#pragma unroll
        for (int nt = 0; nt < 4; ++nt)
#pragma unroll
            for (int c = 0; c < 4; ++c) acc[mt][nt][c] = 0.0f;

    for (int k0 = 0; k0 < K; k0 += 32) {
#pragma unroll
        for (int i = 0; i < 4; ++i) {
            int f = tid + i * 256;               // A tile 128x32
            int r = f >> 3, c4 = (f & 7) * 4;
            float4 v = *(const float4*)&A[(size_t)(rowBlk + r) * K + k0 + c4];
            *(uint4*)&As[r * GSA + c4] =
                make_uint4(f2tf(v.x), f2tf(v.y), f2tf(v.z), f2tf(v.w));
        }
#pragma unroll
        for (int i = 0; i < 4; ++i) {
            int f = tid + i * 256;               // B tile 32x128
            int r = f >> 5, c4 = (f & 31) * 4;
            float4 v = *(const float4*)&Bm[(size_t)(k0 + r) * N + colBlk + c4];
            *(uint4*)&Bs[r * GSB + c4] =
                make_uint4(f2tf(v.x), f2tf(v.y), f2tf(v.z), f2tf(v.w));
        }
        __syncthreads();

#pragma unroll
        for (int ks = 0; ks < 4; ++ks) {
            int kk = ks * 8;
            uint32_t af[4][4];
#pragma unroll
            for (int mt = 0; mt < 4; ++mt) ldm4(af[mt], abase[mt] + 4 * kk);
            uint32_t bf[4][2];
#pragma unroll
            for (int nt = 0; nt < 4; ++nt) {
                bf[nt][0] = Bs[kk * GSB + bb0 + nt * 8];
                bf[nt][1] = Bs[(kk + 4) * GSB + bb0 + nt * 8];
            }
#pragma unroll
            for (int mt = 0; mt < 4; ++mt)
#pragma unroll
                for (int nt = 0; nt < 4; ++nt)
                    mma8(acc[mt][nt], af[mt], bf[nt][0], bf[nt][1]);
        }
        __syncthreads();
    }

#pragma unroll
    for (int mt = 0; mt < 4; ++mt) {
#pragma unroll
        for (int nt = 0; nt < 4; ++nt) {
            int r0 = rowBlk + wm * 64 + mt * 16 + p;
            int c0 = colBlk + wn * 32 + nt * 8 + 2 * q;
            float b0 = bias[c0], b1 = bias[c0 + 1];
            *(float2*)&C[(size_t)r0 * N + c0] =
                make_float2(acc[mt][nt][0] + b0, acc[mt][nt][1] + b1);
            *(float2*)&C[(size_t)(r0 + 8) * N + c0] =
                make_float2(acc[mt][nt][2] + b0, acc[mt][nt][3] + b1);
        }
    }
}

// ---------------- RoPE table ------------------------------------------------
__global__ void rope_table_kernel()
{
    int i = blockIdx.x * blockDim.x + threadIdx.x;
    if (i >= T_SZ * HALF) return;
    int t = i / HALF;
    int d = i % HALF;
    double invf = pow(10000.0, -(double)d / (double)HALF);
    float fr = (float)t * (float)invf;
    g_sin[i] = sinf(fr);
    g_cos[i] = cosf(fr);
}

// ---------------- RoPE apply + relayout -------------------------------------
__global__ void rope_split_kernel()
{
    int idx = blockIdx.x * blockDim.x + threadIdx.x;
    const int TOTAL = B_SZ * T_SZ * HEADS * HALF;
    if (idx >= TOTAL) return;
    int d = idx & (HALF - 1);
    int h = (idx >> 5) & (HEADS - 1);
    int t = (idx >> 9) & (T_SZ - 1);
    int b = idx >> 20;

    float s = g_sin[t * HALF + d];
    float c = g_cos[t * HALF + d];

    size_t row = (size_t)(b * T_SZ + t) * N_QKV;
    size_t orow = (size_t)((b * HEADS + h) * T_SZ + t) * DH;

    const float* qp = g_qkv + row + h * DH;
    float x1 = qp[d], x2 = qp[d + HALF];
    g_q[orow + d]        = x1 * c - x2 * s;
    g_q[orow + d + HALF] = x1 * s + x2 * c;

    const float* kp = g_qkv + row + D_MODEL + h * DH;
    x1 = kp[d]; x2 = kp[d + HALF];
    g_k[orow + d]        = x1 * c - x2 * s;
    g_k[orow + d + HALF] = x1 * s + x2 * c;

    const float* vp = g_qkv + row + 2 * D_MODEL + h * DH;
    g_v[orow + d]        = vp[d];
    g_v[orow + d + HALF] = vp[d + HALF];
}

// ---------------- Flash attention, TF32 MMA + ldmatrix ----------------------
// 128 queries/block, 64 keys/iter, 256 threads = 8 warps; warp owns 16 q-rows.
#define SQ 68
#define SK 68
#define SV 72
#define SP 68
#define OFF_Q 0
#define OFF_K (128 * SQ)
#define OFF_V (OFF_K + 64 * SK)
#define OFF_P (OFF_V + 64 * SV)
#define ATTN_U32 (OFF_P + 128 * SP)
#define ATTN_SMEM (ATTN_U32 * 4)     // 105472 B

__global__ void __launch_bounds__(256, 2) attn_tf32_kernel()
{
    extern __shared__ uint32_t sm[];
    uint32_t* Qs = sm + OFF_Q;
    uint32_t* Ks = sm + OFF_K;
    uint32_t* Vs = sm + OFF_V;
    uint32_t* Ps = sm + OFF_P;

    int tid = threadIdx.x;
    int warp = tid >> 5, lane = tid & 31;
    int p = lane >> 2, q = lane & 3;
    int m0 = warp * 16;
    int bh = blockIdx.y;
    int q0 = blockIdx.x * 128;

    const float* Qb = g_q + ((size_t)bh * T_SZ + q0) * DH;
    const float* Kb = g_k + (size_t)bh * T_SZ * DH;
    const float* Vb = g_v + (size_t)bh * T_SZ * DH;

    uint32_t qbase = sptr(Qs) + 4 * ((m0 + (lane & 15)) * SQ + ((lane >> 4) << 2));
    uint32_t kbase = sptr(Ks) + 4 * (((lane & 15)) * SK + ((lane >> 4) << 2));
    uint32_t pbase = sptr(Ps) + 4 * ((m0 + (lane & 15)) * SP + ((lane >> 4) << 2));
    int vb0 = q * SV + p;

#pragma unroll
    for (int i = 0; i < 8; ++i) {
        int f = tid + i * 256;               // Q 128x64
        int r = f >> 4, c4 = (f & 15) * 4;
        float4 v = *(const float4*)&Qb[r * DH + c4];
        *(uint4*)&Qs[r * SQ + c4] =
            make_uint4(f2tf(v.x), f2tf(v.y), f2tf(v.z), f2tf(v.w));
    }

    float o[8][4];
    float mA = -INFINITY, mB = -INFINITY, lA = 0.0f, lB = 0.0f;
#pragma unroll
    for (int nt = 0; nt < 8; ++nt)
#pragma unroll
        for (int c = 0; c < 4; ++c) o[nt][c] = 0.0f;

    const float scale = 0.125f;

    for (int kt = 0; kt < T_SZ / 64; ++kt) {
        __syncthreads();
        const float* Kp = Kb + (size_t)kt * 64 * DH;
        const float* Vp = Vb + (size_t)kt * 64 * DH;
#pragma unroll
        for (int i = 0; i < 4; ++i) {
            int f = tid + i * 256;           // 64x64 tiles
            int r = f >> 4, c4 = (f & 15) * 4;
            float4 kv = *(const float4*)&Kp[r * DH + c4];
            *(uint4*)&Ks[r * SK + c4] =
                make_uint4(f2tf(kv.x), f2tf(kv.y), f2tf(kv.z), f2tf(kv.w));
            float4 vv = *(const float4*)&Vp[r * DH + c4];
            *(uint4*)&Vs[r * SV + c4] =
                make_uint4(f2tf(vv.x), f2tf(vv.y), f2tf(vv.z), f2tf(vv.w));
        }
        __syncthreads();

        // ---- S = Q K^T : warp computes 16 x 64 ----
        float s[8][4];
#pragma unroll
        for (int nt = 0; nt < 8; ++nt)
#pragma unroll
            for (int c = 0; c < 4; ++c) s[nt][c] = 0.0f;

#pragma unroll
        for (int ks = 0; ks < 8; ++ks) {
            int kk = ks * 8;
            uint32_t a[4];
            ldm4(a, qbase + 4 * kk);
#pragma unroll
            for (int nt2 = 0; nt2 < 4; ++nt2) {
                uint32_t b[4];
                ldm4(b, kbase + 4 * (nt2 * 16 * SK + kk));
                mma8(s[nt2 * 2 + 0], a, b[0], b[2]);
                mma8(s[nt2 * 2 + 1], a, b[1], b[3]);
            }
        }

        // ---- online softmax (rows p and p+8; width-4 shfl) ----
        float mxA = -INFINITY, mxB = -INFINITY;
#pragma unroll
        for (int nt = 0; nt < 8; ++nt) {
            s[nt][0] *= scale; s[nt][1] *= scale;
            s[nt][2] *= scale; s[nt][3] *= scale;
            mxA = fmaxf(mxA, fmaxf(s[nt][0], s[nt][1]));
            mxB = fmaxf(mxB, fmaxf(s[nt][2], s[nt][3]));
        }
        mxA = fmaxf(mxA, __shfl_xor_sync(0xffffffffu, mxA, 1));
        mxA = fmaxf(mxA, __shfl_xor_sync(0xffffffffu, mxA, 2));
        mxB = fmaxf(mxB, __shfl_xor_sync(0xffffffffu, mxB, 1));
        mxB = fmaxf(mxB, __shfl_xor_sync(0xffffffffu, mxB, 2));
        float mnA = fmaxf(mA, mxA), mnB = fmaxf(mB, mxB);
        float cA = __expf(mA - mnA), cB = __expf(mB - mnB);
        mA = mnA; mB = mnB;
        float rsA = 0.0f, rsB = 0.0f;
#pragma unroll
        for (int nt = 0; nt < 8; ++nt) {
            s[nt][0] = __expf(s[nt][0] - mnA); rsA += s[nt][0];
            s[nt][1] = __expf(s[nt][1] - mnA); rsA += s[nt][1];
            s[nt][2] = __expf(s[nt][2] - mnB); rsB += s[nt][2];
            s[nt][3] = __expf(s[nt][3] - mnB); rsB += s[nt][3];
        }
        rsA += __shfl_xor_sync(0xffffffffu, rsA, 1);
        rsA += __shfl_xor_sync(0xffffffffu, rsA, 2);
        rsB += __shfl_xor_sync(0xffffffffu, rsB, 1);
        rsB += __shfl_xor_sync(0xffffffffu, rsB, 2);
        lA = lA * cA + rsA;
        lB = lB * cB + rsB;
#pragma unroll
        for (int nt = 0; nt < 8; ++nt) {
            o[nt][0] *= cA; o[nt][1] *= cA;
            o[nt][2] *= cB; o[nt][3] *= cB;
        }

        // ---- P -> warp-private smem strip (pre-converted to tf32) ----
#pragma unroll
        for (int nt = 0; nt < 8; ++nt) {
            *(uint2*)&Ps[(m0 + p) * SP + nt * 8 + 2 * q] =
                make_uint2(f2tf(s[nt][0]), f2tf(s[nt][1]));
            *(uint2*)&Ps[(m0 + p + 8) * SP + nt * 8 + 2 * q] =
                make_uint2(f2tf(s[nt][2]), f2tf(s[nt][3]));
        }
        __syncwarp();

        // ---- O += P @ V ----
#pragma unroll
        for (int ks = 0; ks < 8; ++ks) {
            int kk = ks * 8;
            uint32_t a[4];
            ldm4(a, pbase + 4 * kk);
#pragma unroll
            for (int nt = 0; nt < 8; ++nt) {
                uint32_t b0 = Vs[kk * SV + vb0 + nt * 8];
                uint32_t b1 = Vs[(kk + 4) * SV + vb0 + nt * 8];
                mma8(o[nt], a, b0, b1);
            }
        }
    }

    // ---- epilogue: normalize, write [b,t,h*dh] ----
    int b_ = bh / HEADS;
    int h_ = bh % HEADS;
    float ivA = 1.0f / lA, ivB = 1.0f / lB;
    int t = q0 + m0 + p;
#pragma unroll
    for (int nt = 0; nt < 8; ++nt) {
        float* op = g_attn + (size_t)(b_ * T_SZ + t) * D_MODEL + h_ * DH + nt * 8 + 2 * q;
        *(float2*)op = make_float2(o[nt][0] * ivA, o[nt][1] * ivA);
        *(float2*)(op + 8 * D_MODEL) = make_float2(o[nt][2] * ivB, o[nt][3] * ivB);
    }
}

// ---------------- launcher --------------------------------------------------
extern "C" void kernel_launch(void* const* d_in, const int* in_sizes, int n_in,
                              void* d_out, int out_size)
{
    const float* x     = (const float*)d_in[0];
    const float* Wqkv  = (const float*)d_in[1];
    const float* bqkv  = (const float*)d_in[2];
    const float* Wproj = (const float*)d_in[3];
    const float* bproj = (const float*)d_in[4];
    float* out = (float*)d_out;

    float* qkv_ptr = nullptr;
    float* attn_ptr = nullptr;
    cudaGetSymbolAddress((void**)&qkv_ptr, g_qkv);
    cudaGetSymbolAddress((void**)&attn_ptr, g_attn);

    cudaFuncSetAttribute(attn_tf32_kernel,
                         cudaFuncAttributeMaxDynamicSharedMemorySize, ATTN_SMEM);

    // 1) QKV GEMM
    {
        dim3 grid(N_QKV / 128, M_ROWS / 128);
        gemm_tf32_kernel<<<grid, 256>>>(x, Wqkv, bqkv, qkv_ptr,
                                        M_ROWS, N_QKV, D_MODEL);
    }
    // 2) RoPE
    {
        int n = T_SZ * HALF;
        rope_table_kernel<<<(n + 255) / 256, 256>>>();
        int total = B_SZ * T_SZ * HEADS * HALF;
        rope_split_kernel<<<(total + 255) / 256, 256>>>();
    }
    // 3) flash attention
    {
        dim3 grid(T_SZ / 128, B_SZ * HEADS);
        attn_tf32_kernel<<<grid, 256, ATTN_SMEM>>>();
    }
    // 4) output projection
    {
        dim3 grid(D_MODEL / 128, M_ROWS / 128);
        gemm_tf32_kernel<<<grid, 256>>>(attn_ptr, Wproj, bproj, out,
                                        M_ROWS, D_MODEL, D_MODEL);
    }
}